// round 2
// baseline (speedup 1.0000x reference)
#include <cuda_runtime.h>
#include <math.h>

// ---------------------------------------------------------------------------
// TransformerBlock: B=4, T=1024, E=1024, NH=16, HD=64, ctx S=77 CD=768, FF=4096
// Round 0 baseline: fp32 tiled GEMMs + batched attention kernels.
// ---------------------------------------------------------------------------

#define B_   4
#define T_   1024
#define E_   1024
#define CD_  768
#define FF_  4096
#define NH_  16
#define HD_  64
#define S_   77
#define BT_  (B_ * T_)      // 4096 token rows
#define BS_  (B_ * S_)      // 308 ctx rows

// ---- scratch (static device globals; allocation is forbidden) -------------
__device__ float g_ln[BT_ * E_];          //  16 MB
__device__ float g_q [BT_ * E_];          //  16 MB
__device__ float g_k [BT_ * E_];          //  16 MB (cross uses first 308 rows)
__device__ float g_v [BT_ * E_];          //  16 MB
__device__ float g_attn[BT_ * E_];        //  16 MB
__device__ float g_h [BT_ * FF_];         //  64 MB (FFN hidden)
__device__ float g_s [(size_t)B_ * NH_ * T_ * T_];  // 256 MB (scores)

// ---------------------------------------------------------------------------
// copy (vectorized)
// ---------------------------------------------------------------------------
__global__ void copy4_kernel(const float4* __restrict__ in, float4* __restrict__ out, int n4) {
    int i = blockIdx.x * blockDim.x + threadIdx.x;
    if (i < n4) out[i] = in[i];
}

// ---------------------------------------------------------------------------
// LayerNorm: one block per row, N = E_ = 1024
// ---------------------------------------------------------------------------
__global__ __launch_bounds__(256) void ln_kernel(
    const float* __restrict__ x, const float* __restrict__ g,
    const float* __restrict__ b, float* __restrict__ out, int N)
{
    int row = blockIdx.x;
    const float* xr = x + (size_t)row * N;
    float* orow = out + (size_t)row * N;
    int t = threadIdx.x;

    float s = 0.f, s2 = 0.f;
    for (int i = t; i < N; i += 256) { float v = xr[i]; s += v; s2 += v * v; }

    __shared__ float rs[256], rs2[256];
    rs[t] = s; rs2[t] = s2; __syncthreads();
    for (int o = 128; o > 0; o >>= 1) {
        if (t < o) { rs[t] += rs[t + o]; rs2[t] += rs2[t + o]; }
        __syncthreads();
    }
    float mean = rs[0] / N;
    float var  = rs2[0] / N - mean * mean;
    float inv  = rsqrtf(var + 1e-5f);

    for (int i = t; i < N; i += 256)
        orow[i] = (xr[i] - mean) * inv * g[i] + b[i];
}

// ---------------------------------------------------------------------------
// Generic GEMM: C = act(A[M,K] @ W[K,N] + bias) + resid
// 64x64x16 tiles, 256 threads, 4x4 per thread. bias/resid optional (nullptr).
// ---------------------------------------------------------------------------
template <bool GELU>
__global__ __launch_bounds__(256) void gemm_kernel(
    const float* __restrict__ A, const float* __restrict__ W,
    const float* __restrict__ bias, const float* __restrict__ resid,
    float* __restrict__ C, int M, int N, int K)
{
    __shared__ float As[16][64];
    __shared__ float Bs[16][65];

    int tid = threadIdx.x;
    int tx = tid & 15, ty = tid >> 4;
    int bm = blockIdx.y * 64, bn = blockIdx.x * 64;

    float acc[4][4] = {};

    for (int k0 = 0; k0 < K; k0 += 16) {
        #pragma unroll
        for (int i = 0; i < 4; i++) {
            int idx = tid + i * 256;                 // 0..1023 over 64x16
            int r = idx >> 4, kk = idx & 15;
            int gm = bm + r;
            As[kk][r] = (gm < M) ? A[(size_t)gm * K + (k0 + kk)] : 0.f;
        }
        #pragma unroll
        for (int i = 0; i < 4; i++) {
            int idx = tid + i * 256;                 // 16x64
            int kk = idx >> 6, c = idx & 63;
            int gn = bn + c;
            Bs[kk][c] = (gn < N) ? W[(size_t)(k0 + kk) * N + gn] : 0.f;
        }
        __syncthreads();
        #pragma unroll
        for (int kk = 0; kk < 16; kk++) {
            float a[4], b[4];
            #pragma unroll
            for (int i = 0; i < 4; i++) a[i] = As[kk][ty * 4 + i];
            #pragma unroll
            for (int j = 0; j < 4; j++) b[j] = Bs[kk][tx * 4 + j];
            #pragma unroll
            for (int i = 0; i < 4; i++)
                #pragma unroll
                for (int j = 0; j < 4; j++)
                    acc[i][j] += a[i] * b[j];
        }
        __syncthreads();
    }

    #pragma unroll
    for (int i = 0; i < 4; i++) {
        int gm = bm + ty * 4 + i;
        if (gm >= M) continue;
        #pragma unroll
        for (int j = 0; j < 4; j++) {
            int gn = bn + tx * 4 + j;
            if (gn >= N) continue;
            float v = acc[i][j];
            if (bias)  v += bias[gn];
            if (GELU)  v = 0.5f * v * (1.0f + erff(v * 0.70710678118654752f));
            if (resid) v += resid[(size_t)gm * N + gn];
            C[(size_t)gm * N + gn] = v;
        }
    }
}

// ---------------------------------------------------------------------------
// Attention scores: Sc[b,h,t,s] = scale * sum_d Q[b,t,h,d] * K[b,s,h,d]
// grid (ceil(Ts/64), T/64, B*NH), 256 thr, full head-dim (64) in smem.
// ---------------------------------------------------------------------------
__global__ __launch_bounds__(256) void scores_kernel(
    const float* __restrict__ Q, const float* __restrict__ Kd,
    float* __restrict__ Sc, int Ts, int kRows, float scale)
{
    int bh = blockIdx.z;
    int b = bh >> 4, h = bh & 15;
    const float* Qb = Q  + (size_t)b * T_ * E_   + h * HD_;
    const float* Kb = Kd + (size_t)b * kRows * E_ + h * HD_;
    float* Sb = Sc + (size_t)bh * T_ * Ts;

    __shared__ float Qs[64][65];
    __shared__ float Ks[64][65];

    int tid = threadIdx.x, tx = tid & 15, ty = tid >> 4;
    int bt = blockIdx.y * 64, bs = blockIdx.x * 64;

    #pragma unroll
    for (int i = 0; i < 16; i++) {
        int idx = tid + i * 256;                     // 64x64
        int r = idx >> 6, d = idx & 63;
        Qs[r][d] = Qb[(size_t)(bt + r) * E_ + d];
        int s = bs + r;
        Ks[r][d] = (s < Ts) ? Kb[(size_t)s * E_ + d] : 0.f;
    }
    __syncthreads();

    float acc[4][4] = {};
    #pragma unroll 8
    for (int d = 0; d < 64; d++) {
        float a[4], bv[4];
        #pragma unroll
        for (int i = 0; i < 4; i++) a[i]  = Qs[ty * 4 + i][d];
        #pragma unroll
        for (int j = 0; j < 4; j++) bv[j] = Ks[tx * 4 + j][d];
        #pragma unroll
        for (int i = 0; i < 4; i++)
            #pragma unroll
            for (int j = 0; j < 4; j++)
                acc[i][j] += a[i] * bv[j];
    }

    #pragma unroll
    for (int i = 0; i < 4; i++) {
        int t = bt + ty * 4 + i;
        #pragma unroll
        for (int j = 0; j < 4; j++) {
            int s = bs + tx * 4 + j;
            if (s < Ts) Sb[(size_t)t * Ts + s] = acc[i][j] * scale;
        }
    }
}

// ---------------------------------------------------------------------------
// Row softmax over length L (<= 1024), one block (256 thr) per row.
// ---------------------------------------------------------------------------
__global__ __launch_bounds__(256) void softmax_kernel(float* __restrict__ Sc, int L)
{
    float* r = Sc + (size_t)blockIdx.x * L;
    __shared__ float buf[1024];
    __shared__ float red[256];
    int t = threadIdx.x;

    float m = -1e30f;
    for (int i = t; i < L; i += 256) { float v = r[i]; buf[i] = v; m = fmaxf(m, v); }
    red[t] = m; __syncthreads();
    for (int o = 128; o > 0; o >>= 1) { if (t < o) red[t] = fmaxf(red[t], red[t + o]); __syncthreads(); }
    m = red[0]; __syncthreads();

    float s = 0.f;
    for (int i = t; i < L; i += 256) { float e = __expf(buf[i] - m); buf[i] = e; s += e; }
    red[t] = s; __syncthreads();
    for (int o = 128; o > 0; o >>= 1) { if (t < o) red[t] += red[t + o]; __syncthreads(); }
    float inv = 1.0f / red[0];

    for (int i = t; i < L; i += 256) r[i] = buf[i] * inv;
}

// ---------------------------------------------------------------------------
// PV: O[b,t,h,d] = sum_s P[b,h,t,s] * V[b,s,h,d];  grid (T/64, B*NH)
// ---------------------------------------------------------------------------
__global__ __launch_bounds__(256) void pv_kernel(
    const float* __restrict__ Sc, const float* __restrict__ V,
    float* __restrict__ O, int L, int kRows)
{
    int bh = blockIdx.y;
    int b = bh >> 4, h = bh & 15;
    const float* Pb = Sc + (size_t)bh * T_ * L;
    const float* Vb = V  + (size_t)b * kRows * E_ + h * HD_;
    float* Ob = O + (size_t)b * T_ * E_ + h * HD_;

    __shared__ float Ps[64][17];
    __shared__ float Vs[16][65];

    int tid = threadIdx.x, tx = tid & 15, ty = tid >> 4;
    int bt = blockIdx.x * 64;

    float acc[4][4] = {};
    for (int k0 = 0; k0 < L; k0 += 16) {
        #pragma unroll
        for (int i = 0; i < 4; i++) {
            int idx = tid + i * 256;                 // 64x16
            int r = idx >> 4, kk = idx & 15;
            int s = k0 + kk;
            Ps[r][kk] = (s < L) ? Pb[(size_t)(bt + r) * L + s] : 0.f;
        }
        #pragma unroll
        for (int i = 0; i < 4; i++) {
            int idx = tid + i * 256;                 // 16x64
            int kk = idx >> 6, d = idx & 63;
            int s = k0 + kk;
            Vs[kk][d] = (s < L) ? Vb[(size_t)s * E_ + d] : 0.f;
        }
        __syncthreads();
        #pragma unroll
        for (int kk = 0; kk < 16; kk++) {
            float a[4], bv[4];
            #pragma unroll
            for (int i = 0; i < 4; i++) a[i]  = Ps[ty * 4 + i][kk];
            #pragma unroll
            for (int j = 0; j < 4; j++) bv[j] = Vs[kk][tx * 4 + j];
            #pragma unroll
            for (int i = 0; i < 4; i++)
                #pragma unroll
                for (int j = 0; j < 4; j++)
                    acc[i][j] += a[i] * bv[j];
        }
        __syncthreads();
    }

    #pragma unroll
    for (int i = 0; i < 4; i++) {
        int t = bt + ty * 4 + i;
        #pragma unroll
        for (int j = 0; j < 4; j++) {
            int d = tx * 4 + j;
            Ob[(size_t)t * E_ + d] = acc[i][j];
        }
    }
}

// ---------------------------------------------------------------------------
// Orchestration
// ---------------------------------------------------------------------------
extern "C" void kernel_launch(void* const* d_in, const int* in_sizes, int n_in,
                              void* d_out, int out_size)
{
    const float* x    = (const float*)d_in[0];
    const float* ctx  = (const float*)d_in[1];
    const float* sq_w = (const float*)d_in[2];
    const float* sk_w = (const float*)d_in[3];
    const float* sv_w = (const float*)d_in[4];
    const float* so_w = (const float*)d_in[5];
    const float* so_b = (const float*)d_in[6];
    const float* cq_w = (const float*)d_in[7];
    const float* ck_w = (const float*)d_in[8];
    const float* cv_w = (const float*)d_in[9];
    const float* co_w = (const float*)d_in[10];
    const float* co_b = (const float*)d_in[11];
    const float* n1_g = (const float*)d_in[12];
    const float* n1_b = (const float*)d_in[13];
    const float* n2_g = (const float*)d_in[14];
    const float* n2_b = (const float*)d_in[15];
    const float* n3_g = (const float*)d_in[16];
    const float* n3_b = (const float*)d_in[17];
    const float* n4_g = (const float*)d_in[18];
    const float* n4_b = (const float*)d_in[19];
    const float* f1_w1 = (const float*)d_in[20];
    const float* f1_b1 = (const float*)d_in[21];
    const float* f1_w2 = (const float*)d_in[22];
    const float* f1_b2 = (const float*)d_in[23];
    const float* f2_w1 = (const float*)d_in[24];
    const float* f2_b1 = (const float*)d_in[25];
    const float* f2_w2 = (const float*)d_in[26];
    const float* f2_b2 = (const float*)d_in[27];

    float *ln, *q, *k, *v, *attn, *h, *sc;
    cudaGetSymbolAddress((void**)&ln,   g_ln);
    cudaGetSymbolAddress((void**)&q,    g_q);
    cudaGetSymbolAddress((void**)&k,    g_k);
    cudaGetSymbolAddress((void**)&v,    g_v);
    cudaGetSymbolAddress((void**)&attn, g_attn);
    cudaGetSymbolAddress((void**)&h,    g_h);
    cudaGetSymbolAddress((void**)&sc,   g_s);

    float* X = (float*)d_out;          // residual accumulator lives in d_out
    const float scale = 0.125f;        // 1/sqrt(64)

    dim3 blk(256);
    dim3 gEE(E_ / 64, BT_ / 64);                    // [4096,1024] x [K,1024]
    dim3 gFF(FF_ / 64, BT_ / 64);                   // FFN up
    dim3 gCK(E_ / 64, (BS_ + 63) / 64);             // ctx projections (M=308)
    dim3 gScSelf(T_ / 64, T_ / 64, B_ * NH_);
    dim3 gScCross((S_ + 63) / 64, T_ / 64, B_ * NH_);
    dim3 gPV(T_ / 64, B_ * NH_);

    // X = x
    copy4_kernel<<<(BT_ * E_ / 4 + 255) / 256, blk>>>((const float4*)x, (float4*)X, BT_ * E_ / 4);

    // ---- self-attention ----
    ln_kernel<<<BT_, blk>>>(X, n1_g, n1_b, ln, E_);
    gemm_kernel<false><<<gEE, blk>>>(ln, sq_w, nullptr, nullptr, q, BT_, E_, E_);
    gemm_kernel<false><<<gEE, blk>>>(ln, sk_w, nullptr, nullptr, k, BT_, E_, E_);
    gemm_kernel<false><<<gEE, blk>>>(ln, sv_w, nullptr, nullptr, v, BT_, E_, E_);
    scores_kernel<<<gScSelf, blk>>>(q, k, sc, T_, T_, scale);
    softmax_kernel<<<B_ * NH_ * T_, blk>>>(sc, T_);
    pv_kernel<<<gPV, blk>>>(sc, v, attn, T_, T_);
    gemm_kernel<false><<<gEE, blk>>>(attn, so_w, so_b, X, X, BT_, E_, E_);

    // ---- FFN 1 ----
    ln_kernel<<<BT_, blk>>>(X, n2_g, n2_b, ln, E_);
    gemm_kernel<true ><<<gFF, blk>>>(ln, f1_w1, f1_b1, nullptr, h, BT_, FF_, E_);
    gemm_kernel<false><<<gEE, blk>>>(h, f1_w2, f1_b2, X, X, BT_, E_, FF_);

    // ---- cross-attention ----
    ln_kernel<<<BT_, blk>>>(X, n3_g, n3_b, ln, E_);
    gemm_kernel<false><<<gEE, blk>>>(ln, cq_w, nullptr, nullptr, q, BT_, E_, E_);
    gemm_kernel<false><<<gCK, blk>>>(ctx, ck_w, nullptr, nullptr, k, BS_, E_, CD_);
    gemm_kernel<false><<<gCK, blk>>>(ctx, cv_w, nullptr, nullptr, v, BS_, E_, CD_);
    scores_kernel<<<gScCross, blk>>>(q, k, sc, S_, S_, scale);
    softmax_kernel<<<B_ * NH_ * T_, blk>>>(sc, S_);
    pv_kernel<<<gPV, blk>>>(sc, v, attn, S_, S_);
    gemm_kernel<false><<<gEE, blk>>>(attn, co_w, co_b, X, X, BT_, E_, E_);

    // ---- FFN 2 ----
    ln_kernel<<<BT_, blk>>>(X, n4_g, n4_b, ln, E_);
    gemm_kernel<true ><<<gFF, blk>>>(ln, f2_w1, f2_b1, nullptr, h, BT_, FF_, E_);
    gemm_kernel<false><<<gEE, blk>>>(h, f2_w2, f2_b2, X, X, BT_, E_, FF_);
}

// round 5
// speedup vs baseline: 3.3404x; 3.3404x over previous
#include <cuda_runtime.h>
#include <cstdint>
#include <math.h>

// ---------------------------------------------------------------------------
// TransformerBlock: B=4, T=1024, E=1024, NH=16, HD=64, ctx S=77 CD=768, FF=4096
// Round 4: mma.sync tf32 (baseline-ISA tensor cores) + cp.async pipeline.
// ---------------------------------------------------------------------------

#define B_   4
#define T_   1024
#define E_   1024
#define CD_  768
#define FF_  4096
#define NH_  16
#define HD_  64
#define S_   77
#define SP_  128
#define BT_  (B_ * T_)
#define BS_  (B_ * S_)

// ---- scratch --------------------------------------------------------------
__device__ float g_ln[BT_ * E_];
__device__ float g_q [BT_ * E_];
__device__ float g_k [BT_ * E_];
__device__ float g_v [BT_ * E_];
__device__ float g_attn[BT_ * E_];
__device__ float g_h [BT_ * FF_];
__device__ float g_s [(size_t)B_ * NH_ * T_ * T_];
__device__ float g_vts[(size_t)B_ * NH_ * HD_ * T_];
__device__ float g_vtc[(size_t)B_ * NH_ * HD_ * SP_];
__device__ float g_wt[24 * 1024 * 1024];

#define WT_SQ   (0)
#define WT_SK   (1*1024*1024)
#define WT_SV   (2*1024*1024)
#define WT_SO   (3*1024*1024)
#define WT_CQ   (4*1024*1024)
#define WT_CK   (5*1024*1024)
#define WT_CV   (6*1024*1024)
#define WT_CO   (7*1024*1024)
#define WT_F1A  (8*1024*1024)
#define WT_F1B  (12*1024*1024)
#define WT_F2A  (16*1024*1024)
#define WT_F2B  (20*1024*1024)

// ---------------------------------------------------------------------------
// PTX helpers (baseline ISA: cp.async + mma.sync tf32)
// ---------------------------------------------------------------------------
__device__ __forceinline__ uint32_t s2u(const void* p) {
    uint32_t a;
    asm("{ .reg .u64 t; cvta.to.shared.u64 t, %1; cvt.u32.u64 %0, t; }" : "=r"(a) : "l"(p));
    return a;
}
#define CP16(dst, src, sz) \
    asm volatile("cp.async.cg.shared.global [%0], [%1], 16, %2;" \
                 :: "r"(dst), "l"(src), "r"(sz) : "memory")
#define CP_COMMIT() asm volatile("cp.async.commit_group;" ::: "memory")
#define CP_WAIT(n)  asm volatile("cp.async.wait_group %0;" :: "n"(n) : "memory")

__device__ __forceinline__ uint32_t f2tf(float f) {
    uint32_t u;
    asm("cvt.rna.tf32.f32 %0, %1;" : "=r"(u) : "f"(f));
    return u;
}
__device__ __forceinline__ void mma8(float* c, const uint32_t* a, const uint32_t* b) {
    asm volatile(
        "mma.sync.aligned.m16n8k8.row.col.f32.tf32.tf32.f32 "
        "{%0,%1,%2,%3},{%4,%5,%6,%7},{%8,%9},{%0,%1,%2,%3};"
        : "+f"(c[0]), "+f"(c[1]), "+f"(c[2]), "+f"(c[3])
        : "r"(a[0]), "r"(a[1]), "r"(a[2]), "r"(a[3]), "r"(b[0]), "r"(b[1]));
}

// ---------------------------------------------------------------------------
// tf32 GEMM: D[m,n] = sum_k A[m,k] * B[n,k]   (B given K-major, i.e. W^T)
// CTA tile 128x128, K-chunk 32, 8 warps (2x4), warp tile 64x32, 2-stage cp.async.
// ---------------------------------------------------------------------------
#define PAD_  36                      // smem row stride in floats
#define AS_   (128 * PAD_)            // floats per stage-half
#define SMEMSZ_ (4 * AS_ * 4)         // bytes: A0,B0,A1,B1

template <bool GELU>
__global__ __launch_bounds__(256) void mm_kernel(
    const float* __restrict__ A, const float* __restrict__ Bm,
    const float* __restrict__ bias, const float* __restrict__ resid,
    float* __restrict__ C,
    int M, int Nload, int Nstore, int Kch, int lda, int ldb, int ldc,
    long long aOuter, long long aInner, long long bOuter, long long bInner,
    long long cOuter, long long cInner, int NHz, float scale)
{
    extern __shared__ float smem[];
    const uint32_t sbase = s2u(smem);

    const int tid = threadIdx.x;
    const int wid = tid >> 5, lane = tid & 31;
    const int grp = lane >> 2, tig = lane & 3;
    const int mW = (wid >> 2) * 64, nW = (wid & 3) * 32;

    const int z = blockIdx.z;
    const int zb = z / NHz, zh = z % NHz;
    const float* Ab = A + zb * aOuter + zh * aInner;
    const float* Bb = Bm + zb * bOuter + zh * bInner;
    float* Cb = C + zb * cOuter + zh * cInner;
    const float* Rb = resid ? resid + zb * cOuter + zh * cInner : nullptr;

    const int bm = blockIdx.y * 128, bn = blockIdx.x * 128;

    float acc[4][4][4];
    #pragma unroll
    for (int i = 0; i < 4; i++)
        #pragma unroll
        for (int j = 0; j < 4; j++)
            #pragma unroll
            for (int e = 0; e < 4; e++) acc[i][j][e] = 0.f;

    // ---- chunk loader: A/B 128x32 into stage st ----
    auto loadChunk = [&](int ic, int st) {
        const int k0 = ic * 32;
        const uint32_t aB = sbase + (uint32_t)st * 2u * AS_ * 4u;
        const uint32_t bB = aB + AS_ * 4u;
        #pragma unroll
        for (int i = 0; i < 4; i++) {
            int seg = tid + i * 256;
            int row = seg >> 3, s = seg & 7;
            int gm = bm + row;
            const float* srcA = Ab + (size_t)(gm < M ? gm : 0) * lda + k0 + s * 4;
            CP16(aB + (uint32_t)(row * PAD_ + s * 4) * 4u, srcA, (gm < M) ? 16 : 0);
            int gn = bn + row;
            const float* srcB = Bb + (size_t)(gn < Nload ? gn : 0) * ldb + k0 + s * 4;
            CP16(bB + (uint32_t)(row * PAD_ + s * 4) * 4u, srcB, (gn < Nload) ? 16 : 0);
        }
        CP_COMMIT();
    };

    loadChunk(0, 0);

    for (int ic = 0; ic < Kch; ic++) {
        const int st = ic & 1;
        if (ic + 1 < Kch) { loadChunk(ic + 1, st ^ 1); CP_WAIT(1); }
        else             { CP_WAIT(0); }
        __syncthreads();

        const float* As_ = smem + st * 2 * AS_;
        const float* Bs_ = As_ + AS_;

        #pragma unroll
        for (int k8 = 0; k8 < 4; k8++) {
            const int k = k8 * 8 + tig;
            uint32_t af[4][4], bf[4][2];
            #pragma unroll
            for (int mt = 0; mt < 4; mt++) {
                int r = mW + mt * 16 + grp;
                af[mt][0] = f2tf(As_[r * PAD_ + k]);
                af[mt][1] = f2tf(As_[(r + 8) * PAD_ + k]);
                af[mt][2] = f2tf(As_[r * PAD_ + k + 4]);
                af[mt][3] = f2tf(As_[(r + 8) * PAD_ + k + 4]);
            }
            #pragma unroll
            for (int nt = 0; nt < 4; nt++) {
                int n = nW + nt * 8 + grp;
                bf[nt][0] = f2tf(Bs_[n * PAD_ + k]);
                bf[nt][1] = f2tf(Bs_[n * PAD_ + k + 4]);
            }
            #pragma unroll
            for (int mt = 0; mt < 4; mt++)
                #pragma unroll
                for (int nt = 0; nt < 4; nt++)
                    mma8(acc[mt][nt], af[mt], bf[nt]);
        }
        __syncthreads();
    }

    // ---- epilogue ----
    #pragma unroll
    for (int mt = 0; mt < 4; mt++) {
        #pragma unroll
        for (int half = 0; half < 2; half++) {
            int row = bm + mW + mt * 16 + grp + half * 8;
            if (row >= M) continue;
            float* crow = Cb + (size_t)row * ldc;
            const float* rrow = Rb ? Rb + (size_t)row * ldc : nullptr;
            #pragma unroll
            for (int nt = 0; nt < 4; nt++) {
                int col = bn + nW + nt * 8 + 2 * tig;
                if (col >= Nstore) continue;
                float v0 = acc[mt][nt][half * 2 + 0] * scale;
                float v1 = acc[mt][nt][half * 2 + 1] * scale;
                if (bias) { v0 += bias[col]; v1 += bias[col + 1]; }
                if (GELU) {
                    v0 = 0.5f * v0 * (1.0f + erff(v0 * 0.70710678118654752f));
                    v1 = 0.5f * v1 * (1.0f + erff(v1 * 0.70710678118654752f));
                }
                if (col + 1 < Nstore) {
                    if (rrow) { float2 rr = *(const float2*)(rrow + col); v0 += rr.x; v1 += rr.y; }
                    *(float2*)(crow + col) = make_float2(v0, v1);
                } else {
                    if (rrow) v0 += rrow[col];
                    crow[col] = v0;
                }
            }
        }
    }
}

// ---------------------------------------------------------------------------
// Transpose (batched), block (32,8)
// ---------------------------------------------------------------------------
__global__ void transpose_kernel(
    const float* __restrict__ in, float* __restrict__ out,
    int R, int C, int ldi, int ldo,
    long long iOuter, long long iInner, long long oOuter, long long oInner, int NHz)
{
    __shared__ float t[32][33];
    int z = blockIdx.z, zb = z / NHz, zh = z % NHz;
    const float* ib = in + zb * iOuter + zh * iInner;
    float* ob = out + zb * oOuter + zh * oInner;
    int c0 = blockIdx.x * 32, r0 = blockIdx.y * 32;
    int x = threadIdx.x, y = threadIdx.y;
    #pragma unroll
    for (int j = 0; j < 32; j += 8) {
        int r = r0 + y + j, c = c0 + x;
        t[y + j][x] = (r < R && c < C) ? ib[(size_t)r * ldi + c] : 0.f;
    }
    __syncthreads();
    #pragma unroll
    for (int j = 0; j < 32; j += 8) {
        int oc = r0 + x, orow = c0 + y + j;
        if (orow < C && oc < R) ob[(size_t)orow * ldo + oc] = t[x][y + j];
    }
}

// ---------------------------------------------------------------------------
// copy / LayerNorm / softmax
// ---------------------------------------------------------------------------
__global__ void copy4_kernel(const float4* __restrict__ in, float4* __restrict__ out, int n4) {
    int i = blockIdx.x * blockDim.x + threadIdx.x;
    if (i < n4) out[i] = in[i];
}

__global__ __launch_bounds__(256) void ln_kernel(
    const float* __restrict__ x, const float* __restrict__ g,
    const float* __restrict__ b, float* __restrict__ out, int N)
{
    int row = blockIdx.x;
    const float* xr = x + (size_t)row * N;
    float* orow = out + (size_t)row * N;
    int t = threadIdx.x;
    float s = 0.f, s2 = 0.f;
    for (int i = t; i < N; i += 256) { float v = xr[i]; s += v; s2 += v * v; }
    __shared__ float rs[256], rs2[256];
    rs[t] = s; rs2[t] = s2; __syncthreads();
    for (int o = 128; o > 0; o >>= 1) {
        if (t < o) { rs[t] += rs[t + o]; rs2[t] += rs2[t + o]; }
        __syncthreads();
    }
    float mean = rs[0] / N;
    float var = rs2[0] / N - mean * mean;
    float inv = rsqrtf(var + 1e-5f);
    for (int i = t; i < N; i += 256)
        orow[i] = (xr[i] - mean) * inv * g[i] + b[i];
}

__global__ __launch_bounds__(256) void softmax_kernel(
    float* __restrict__ Sc, int L, int Lpad, int stride)
{
    float* r = Sc + (size_t)blockIdx.x * stride;
    __shared__ float buf[1024];
    __shared__ float red[256];
    int t = threadIdx.x;
    float m = -1e30f;
    for (int i = t; i < L; i += 256) { float v = r[i]; buf[i] = v; m = fmaxf(m, v); }
    red[t] = m; __syncthreads();
    for (int o = 128; o > 0; o >>= 1) { if (t < o) red[t] = fmaxf(red[t], red[t + o]); __syncthreads(); }
    m = red[0]; __syncthreads();
    float s = 0.f;
    for (int i = t; i < L; i += 256) { float e = __expf(buf[i] - m); buf[i] = e; s += e; }
    red[t] = s; __syncthreads();
    for (int o = 128; o > 0; o >>= 1) { if (t < o) red[t] += red[t + o]; __syncthreads(); }
    float inv = 1.0f / red[0];
    for (int i = t; i < Lpad; i += 256) r[i] = (i < L) ? buf[i] * inv : 0.f;
}

// ---------------------------------------------------------------------------
// Orchestration
// ---------------------------------------------------------------------------
extern "C" void kernel_launch(void* const* d_in, const int* in_sizes, int n_in,
                              void* d_out, int out_size)
{
    const float* x    = (const float*)d_in[0];
    const float* ctx  = (const float*)d_in[1];
    const float* sq_w = (const float*)d_in[2];
    const float* sk_w = (const float*)d_in[3];
    const float* sv_w = (const float*)d_in[4];
    const float* so_w = (const float*)d_in[5];
    const float* so_b = (const float*)d_in[6];
    const float* cq_w = (const float*)d_in[7];
    const float* ck_w = (const float*)d_in[8];
    const float* cv_w = (const float*)d_in[9];
    const float* co_w = (const float*)d_in[10];
    const float* co_b = (const float*)d_in[11];
    const float* n1_g = (const float*)d_in[12];
    const float* n1_b = (const float*)d_in[13];
    const float* n2_g = (const float*)d_in[14];
    const float* n2_b = (const float*)d_in[15];
    const float* n3_g = (const float*)d_in[16];
    const float* n3_b = (const float*)d_in[17];
    const float* n4_g = (const float*)d_in[18];
    const float* n4_b = (const float*)d_in[19];
    const float* f1_w1 = (const float*)d_in[20];
    const float* f1_b1 = (const float*)d_in[21];
    const float* f1_w2 = (const float*)d_in[22];
    const float* f1_b2 = (const float*)d_in[23];
    const float* f2_w1 = (const float*)d_in[24];
    const float* f2_b1 = (const float*)d_in[25];
    const float* f2_w2 = (const float*)d_in[26];
    const float* f2_b2 = (const float*)d_in[27];

    float *ln, *q, *k, *v, *attn, *h, *sc, *vts, *vtc, *wt;
    cudaGetSymbolAddress((void**)&ln,   g_ln);
    cudaGetSymbolAddress((void**)&q,    g_q);
    cudaGetSymbolAddress((void**)&k,    g_k);
    cudaGetSymbolAddress((void**)&v,    g_v);
    cudaGetSymbolAddress((void**)&attn, g_attn);
    cudaGetSymbolAddress((void**)&h,    g_h);
    cudaGetSymbolAddress((void**)&sc,   g_s);
    cudaGetSymbolAddress((void**)&vts,  g_vts);
    cudaGetSymbolAddress((void**)&vtc,  g_vtc);
    cudaGetSymbolAddress((void**)&wt,   g_wt);

    cudaFuncSetAttribute(mm_kernel<false>, cudaFuncAttributeMaxDynamicSharedMemorySize, SMEMSZ_);
    cudaFuncSetAttribute(mm_kernel<true >, cudaFuncAttributeMaxDynamicSharedMemorySize, SMEMSZ_);

    float* X = (float*)d_out;
    const float scale = 0.125f;

    dim3 tb(32, 8);
    auto TW = [&](const float* w, float* o, int R, int C) {
        transpose_kernel<<<dim3((C + 31) / 32, (R + 31) / 32, 1), tb>>>(
            w, o, R, C, C, R, 0, 0, 0, 0, 1);
    };
    TW(sq_w, wt + WT_SQ, E_, E_);   TW(sk_w, wt + WT_SK, E_, E_);
    TW(sv_w, wt + WT_SV, E_, E_);   TW(so_w, wt + WT_SO, E_, E_);
    TW(cq_w, wt + WT_CQ, E_, E_);   TW(ck_w, wt + WT_CK, CD_, E_);
    TW(cv_w, wt + WT_CV, CD_, E_);  TW(co_w, wt + WT_CO, E_, E_);
    TW(f1_w1, wt + WT_F1A, E_, FF_); TW(f1_w2, wt + WT_F1B, FF_, E_);
    TW(f2_w1, wt + WT_F2A, E_, FF_); TW(f2_w2, wt + WT_F2B, FF_, E_);

    copy4_kernel<<<(BT_ * E_ / 4 + 255) / 256, 256>>>((const float4*)x, (float4*)X, BT_ * E_ / 4);

    // plain GEMM: C[M,N] = A[M,K] @ W  (W^T supplied), optional bias/gelu/resid
    auto MM = [&](const float* A, const float* Bt, const float* bias,
                  const float* resid, float* C, int M, int N, int K,
                  int lda, int ldc, bool gelu) {
        dim3 g((N + 127) / 128, (M + 127) / 128, 1);
        if (gelu)
            mm_kernel<true><<<g, 256, SMEMSZ_>>>(A, Bt, bias, resid, C,
                M, N, N, K / 32, lda, K, ldc, 0, 0, 0, 0, 0, 0, 1, 1.f);
        else
            mm_kernel<false><<<g, 256, SMEMSZ_>>>(A, Bt, bias, resid, C,
                M, N, N, K / 32, lda, K, ldc, 0, 0, 0, 0, 0, 0, 1, 1.f);
    };

    const long long TE = (long long)T_ * E_;

    // ================= self-attention =================
    ln_kernel<<<BT_, 256>>>(X, n1_g, n1_b, ln, E_);
    MM(ln, wt + WT_SQ, nullptr, nullptr, q, BT_, E_, E_, E_, E_, false);
    MM(ln, wt + WT_SK, nullptr, nullptr, k, BT_, E_, E_, E_, E_, false);
    MM(ln, wt + WT_SV, nullptr, nullptr, v, BT_, E_, E_, E_, E_, false);
    transpose_kernel<<<dim3(2, 32, B_ * NH_), tb>>>(v, vts, T_, HD_, E_, T_,
        TE, HD_, (long long)NH_ * HD_ * T_, (long long)HD_ * T_, NH_);
    // scores[t,s] = scale * sum_d Q[t,d] K[s,d]
    mm_kernel<false><<<dim3(8, 8, B_ * NH_), 256, SMEMSZ_>>>(q, k, nullptr, nullptr, sc,
        T_, T_, T_, HD_ / 32, E_, E_, T_,
        TE, HD_, TE, HD_, (long long)NH_ * T_ * T_, (long long)T_ * T_, NH_, scale);
    softmax_kernel<<<B_ * NH_ * T_, 256>>>(sc, T_, T_, T_);
    // PV[t,d] = sum_s P[t,s] VT[d,s]
    mm_kernel<false><<<dim3(1, 8, B_ * NH_), 256, SMEMSZ_>>>(sc, vts, nullptr, nullptr, attn,
        T_, HD_, HD_, T_ / 32, T_, T_, E_,
        (long long)NH_ * T_ * T_, (long long)T_ * T_,
        (long long)NH_ * HD_ * T_, (long long)HD_ * T_, TE, HD_, NH_, 1.f);
    MM(attn, wt + WT_SO, so_b, X, X, BT_, E_, E_, E_, E_, false);

    // ================= FFN 1 =================
    ln_kernel<<<BT_, 256>>>(X, n2_g, n2_b, ln, E_);
    MM(ln, wt + WT_F1A, f1_b1, nullptr, h, BT_, FF_, E_, E_, FF_, true);
    MM(h, wt + WT_F1B, f1_b2, X, X, BT_, E_, FF_, FF_, E_, false);

    // ================= cross-attention =================
    ln_kernel<<<BT_, 256>>>(X, n3_g, n3_b, ln, E_);
    MM(ln, wt + WT_CQ, nullptr, nullptr, q, BT_, E_, E_, E_, E_, false);
    MM(ctx, wt + WT_CK, nullptr, nullptr, k, BS_, E_, CD_, CD_, E_, false);
    MM(ctx, wt + WT_CV, nullptr, nullptr, v, BS_, E_, CD_, CD_, E_, false);
    cudaMemsetAsync(vtc, 0, (size_t)B_ * NH_ * HD_ * SP_ * sizeof(float));
    transpose_kernel<<<dim3(2, 3, B_ * NH_), tb>>>(v, vtc, S_, HD_, E_, SP_,
        (long long)S_ * E_, HD_, (long long)NH_ * HD_ * SP_, (long long)HD_ * SP_, NH_);
    // cross scores: Nload=77 (zero-fill pad), Nstore=128 (padded buffer)
    mm_kernel<false><<<dim3(1, 8, B_ * NH_), 256, SMEMSZ_>>>(q, k, nullptr, nullptr, sc,
        T_, S_, SP_, HD_ / 32, E_, E_, SP_,
        TE, HD_, (long long)S_ * E_, HD_,
        (long long)NH_ * T_ * SP_, (long long)T_ * SP_, NH_, scale);
    softmax_kernel<<<B_ * NH_ * T_, 256>>>(sc, S_, SP_, SP_);
    mm_kernel<false><<<dim3(1, 8, B_ * NH_), 256, SMEMSZ_>>>(sc, vtc, nullptr, nullptr, attn,
        T_, HD_, HD_, SP_ / 32, SP_, SP_, E_,
        (long long)NH_ * T_ * SP_, (long long)T_ * SP_,
        (long long)NH_ * HD_ * SP_, (long long)HD_ * SP_, TE, HD_, NH_, 1.f);
    MM(attn, wt + WT_CO, co_b, X, X, BT_, E_, E_, E_, E_, false);

    // ================= FFN 2 =================
    ln_kernel<<<BT_, 256>>>(X, n4_g, n4_b, ln, E_);
    MM(ln, wt + WT_F2A, f2_b1, nullptr, h, BT_, FF_, E_, E_, FF_, true);
    MM(h, wt + WT_F2B, f2_b2, X, X, BT_, E_, FF_, FF_, E_, false);
}

// round 6
// speedup vs baseline: 4.5607x; 1.3653x over previous
#include <cuda_runtime.h>
#include <cstdint>
#include <math.h>

// ---------------------------------------------------------------------------
// TransformerBlock: B=4, T=1024, E=1024, NH=16, HD=64, ctx S=77 CD=768, FF=4096
// Round 5: mma.sync tf32; operands pre-rounded to tf32 at production time
// (no cvt in GEMM mainloop). x->X copy folded into first residual GEMM.
// ---------------------------------------------------------------------------

#define B_   4
#define T_   1024
#define E_   1024
#define CD_  768
#define FF_  4096
#define NH_  16
#define HD_  64
#define S_   77
#define SP_  128
#define BT_  (B_ * T_)
#define BS_  (B_ * S_)

// ---- scratch --------------------------------------------------------------
__device__ float g_ln[BT_ * E_];
__device__ float g_q [BT_ * E_];
__device__ float g_k [BT_ * E_];
__device__ float g_v [BT_ * E_];
__device__ float g_attn[BT_ * E_];
__device__ float g_h [BT_ * FF_];
__device__ float g_s [(size_t)B_ * NH_ * T_ * T_];
__device__ float g_vts[(size_t)B_ * NH_ * HD_ * T_];
__device__ float g_vtc[(size_t)B_ * NH_ * HD_ * SP_];
__device__ float g_ctx[BS_ * CD_];
__device__ float g_wt[24 * 1024 * 1024];

#define WT_SQ   (0)
#define WT_SK   (1*1024*1024)
#define WT_SV   (2*1024*1024)
#define WT_SO   (3*1024*1024)
#define WT_CQ   (4*1024*1024)
#define WT_CK   (5*1024*1024)
#define WT_CV   (6*1024*1024)
#define WT_CO   (7*1024*1024)
#define WT_F1A  (8*1024*1024)
#define WT_F1B  (12*1024*1024)
#define WT_F2A  (16*1024*1024)
#define WT_F2B  (20*1024*1024)

// ---------------------------------------------------------------------------
// PTX helpers
// ---------------------------------------------------------------------------
__device__ __forceinline__ uint32_t s2u(const void* p) {
    uint32_t a;
    asm("{ .reg .u64 t; cvta.to.shared.u64 t, %1; cvt.u32.u64 %0, t; }" : "=r"(a) : "l"(p));
    return a;
}
#define CP16(dst, src, sz) \
    asm volatile("cp.async.cg.shared.global [%0], [%1], 16, %2;" \
                 :: "r"(dst), "l"(src), "r"(sz) : "memory")
#define CP_COMMIT() asm volatile("cp.async.commit_group;" ::: "memory")
#define CP_WAIT(n)  asm volatile("cp.async.wait_group %0;" :: "n"(n) : "memory")

__device__ __forceinline__ float tfr(float f) {       // round to tf32-representable
    uint32_t u;
    asm("cvt.rna.tf32.f32 %0, %1;" : "=r"(u) : "f"(f));
    return __uint_as_float(u);
}
__device__ __forceinline__ void mma8(float* c, const uint32_t* a, const uint32_t* b) {
    asm volatile(
        "mma.sync.aligned.m16n8k8.row.col.f32.tf32.tf32.f32 "
        "{%0,%1,%2,%3},{%4,%5,%6,%7},{%8,%9},{%0,%1,%2,%3};"
        : "+f"(c[0]), "+f"(c[1]), "+f"(c[2]), "+f"(c[3])
        : "r"(a[0]), "r"(a[1]), "r"(a[2]), "r"(a[3]), "r"(b[0]), "r"(b[1]));
}

// ---------------------------------------------------------------------------
// tf32 GEMM: D[m,n] = sum_k A[m,k] * B[n,k]. Operands MUST be pre-rounded
// to tf32-representable floats. CTA 128x128, K-chunk 32, 8 warps, 2-stage.
// ---------------------------------------------------------------------------
#define PAD_  36
#define AS_   (128 * PAD_)
#define SMEMSZ_ (4 * AS_ * 4)

template <bool GELU, bool ROUND>
__global__ __launch_bounds__(256) void mm_kernel(
    const float* __restrict__ A, const float* __restrict__ Bm,
    const float* __restrict__ bias, const float* __restrict__ resid,
    float* __restrict__ C,
    int M, int Nload, int Nstore, int Kch, int lda, int ldb, int ldc,
    long long aOuter, long long aInner, long long bOuter, long long bInner,
    long long cOuter, long long cInner, int NHz, float scale)
{
    extern __shared__ float smem[];
    const uint32_t sbase = s2u(smem);

    const int tid = threadIdx.x;
    const int wid = tid >> 5, lane = tid & 31;
    const int grp = lane >> 2, tig = lane & 3;
    const int mW = (wid >> 2) * 64, nW = (wid & 3) * 32;

    const int z = blockIdx.z;
    const int zb = z / NHz, zh = z % NHz;
    const float* Ab = A + zb * aOuter + zh * aInner;
    const float* Bb = Bm + zb * bOuter + zh * bInner;
    float* Cb = C + zb * cOuter + zh * cInner;
    const float* Rb = resid ? resid + zb * cOuter + zh * cInner : nullptr;

    const int bm = blockIdx.y * 128, bn = blockIdx.x * 128;

    float acc[4][4][4];
    #pragma unroll
    for (int i = 0; i < 4; i++)
        #pragma unroll
        for (int j = 0; j < 4; j++)
            #pragma unroll
            for (int e = 0; e < 4; e++) acc[i][j][e] = 0.f;

    auto loadChunk = [&](int ic, int st) {
        const int k0 = ic * 32;
        const uint32_t aB = sbase + (uint32_t)st * 2u * AS_ * 4u;
        const uint32_t bB = aB + AS_ * 4u;
        #pragma unroll
        for (int i = 0; i < 4; i++) {
            int seg = tid + i * 256;
            int row = seg >> 3, s = seg & 7;
            int gm = bm + row;
            const float* srcA = Ab + (size_t)(gm < M ? gm : 0) * lda + k0 + s * 4;
            CP16(aB + (uint32_t)(row * PAD_ + s * 4) * 4u, srcA, (gm < M) ? 16 : 0);
            int gn = bn + row;
            const float* srcB = Bb + (size_t)(gn < Nload ? gn : 0) * ldb + k0 + s * 4;
            CP16(bB + (uint32_t)(row * PAD_ + s * 4) * 4u, srcB, (gn < Nload) ? 16 : 0);
        }
        CP_COMMIT();
    };

    loadChunk(0, 0);

    for (int ic = 0; ic < Kch; ic++) {
        const int st = ic & 1;
        if (ic + 1 < Kch) { loadChunk(ic + 1, st ^ 1); CP_WAIT(1); }
        else             { CP_WAIT(0); }
        __syncthreads();

        const float* As_ = smem + st * 2 * AS_;
        const float* Bs_ = As_ + AS_;

        #pragma unroll
        for (int k8 = 0; k8 < 4; k8++) {
            const int k = k8 * 8 + tig;
            uint32_t af[4][4], bf[4][2];
            #pragma unroll
            for (int mt = 0; mt < 4; mt++) {
                int r = mW + mt * 16 + grp;
                af[mt][0] = *(const uint32_t*)&As_[r * PAD_ + k];
                af[mt][1] = *(const uint32_t*)&As_[(r + 8) * PAD_ + k];
                af[mt][2] = *(const uint32_t*)&As_[r * PAD_ + k + 4];
                af[mt][3] = *(const uint32_t*)&As_[(r + 8) * PAD_ + k + 4];
            }
            #pragma unroll
            for (int nt = 0; nt < 4; nt++) {
                int n = nW + nt * 8 + grp;
                bf[nt][0] = *(const uint32_t*)&Bs_[n * PAD_ + k];
                bf[nt][1] = *(const uint32_t*)&Bs_[n * PAD_ + k + 4];
            }
            #pragma unroll
            for (int mt = 0; mt < 4; mt++)
                #pragma unroll
                for (int nt = 0; nt < 4; nt++)
                    mma8(acc[mt][nt], af[mt], bf[nt]);
        }
        __syncthreads();
    }

    // ---- epilogue ----
    #pragma unroll
    for (int mt = 0; mt < 4; mt++) {
        #pragma unroll
        for (int half = 0; half < 2; half++) {
            int row = bm + mW + mt * 16 + grp + half * 8;
            if (row >= M) continue;
            float* crow = Cb + (size_t)row * ldc;
            const float* rrow = Rb ? Rb + (size_t)row * ldc : nullptr;
            #pragma unroll
            for (int nt = 0; nt < 4; nt++) {
                int col = bn + nW + nt * 8 + 2 * tig;
                if (col >= Nstore) continue;
                float v0 = acc[mt][nt][half * 2 + 0] * scale;
                float v1 = acc[mt][nt][half * 2 + 1] * scale;
                if (bias) { v0 += bias[col]; v1 += bias[col + 1]; }
                if (GELU) {
                    v0 = 0.5f * v0 * (1.0f + erff(v0 * 0.70710678118654752f));
                    v1 = 0.5f * v1 * (1.0f + erff(v1 * 0.70710678118654752f));
                }
                if (ROUND) { v0 = tfr(v0); v1 = tfr(v1); }
                if (col + 1 < Nstore) {
                    if (rrow) { float2 rr = *(const float2*)(rrow + col); v0 += rr.x; v1 += rr.y; }
                    *(float2*)(crow + col) = make_float2(v0, v1);
                } else {
                    if (rrow) v0 += rrow[col];
                    crow[col] = v0;
                }
            }
        }
    }
}

// ---------------------------------------------------------------------------
// Transpose (batched), rounds to tf32 on write.
// ---------------------------------------------------------------------------
__global__ void transpose_kernel(
    const float* __restrict__ in, float* __restrict__ out,
    int R, int C, int ldi, int ldo,
    long long iOuter, long long iInner, long long oOuter, long long oInner, int NHz)
{
    __shared__ float t[32][33];
    int z = blockIdx.z, zb = z / NHz, zh = z % NHz;
    const float* ib = in + zb * iOuter + zh * iInner;
    float* ob = out + zb * oOuter + zh * oInner;
    int c0 = blockIdx.x * 32, r0 = blockIdx.y * 32;
    int x = threadIdx.x, y = threadIdx.y;
    #pragma unroll
    for (int j = 0; j < 32; j += 8) {
        int r = r0 + y + j, c = c0 + x;
        t[y + j][x] = (r < R && c < C) ? ib[(size_t)r * ldi + c] : 0.f;
    }
    __syncthreads();
    #pragma unroll
    for (int j = 0; j < 32; j += 8) {
        int oc = r0 + x, orow = c0 + y + j;
        if (orow < C && oc < R) ob[(size_t)orow * ldo + oc] = tfr(t[x][y + j]);
    }
}

// round-copy (for ctx)
__global__ void roundcopy4_kernel(const float4* __restrict__ in, float4* __restrict__ out, int n4) {
    int i = blockIdx.x * blockDim.x + threadIdx.x;
    if (i < n4) {
        float4 v = in[i];
        out[i] = make_float4(tfr(v.x), tfr(v.y), tfr(v.z), tfr(v.w));
    }
}

// ---------------------------------------------------------------------------
// LayerNorm (rounds output) / softmax (rounds output)
// ---------------------------------------------------------------------------
__global__ __launch_bounds__(256) void ln_kernel(
    const float* __restrict__ x, const float* __restrict__ g,
    const float* __restrict__ b, float* __restrict__ out, int N)
{
    int row = blockIdx.x;
    const float* xr = x + (size_t)row * N;
    float* orow = out + (size_t)row * N;
    int t = threadIdx.x;
    float s = 0.f, s2 = 0.f;
    for (int i = t; i < N; i += 256) { float v = xr[i]; s += v; s2 += v * v; }
    __shared__ float rs[256], rs2[256];
    rs[t] = s; rs2[t] = s2; __syncthreads();
    for (int o = 128; o > 0; o >>= 1) {
        if (t < o) { rs[t] += rs[t + o]; rs2[t] += rs2[t + o]; }
        __syncthreads();
    }
    float mean = rs[0] / N;
    float var = rs2[0] / N - mean * mean;
    float inv = rsqrtf(var + 1e-5f);
    for (int i = t; i < N; i += 256)
        orow[i] = tfr((xr[i] - mean) * inv * g[i] + b[i]);
}

__global__ __launch_bounds__(256) void softmax_kernel(
    float* __restrict__ Sc, int L, int Lpad, int stride)
{
    float* r = Sc + (size_t)blockIdx.x * stride;
    __shared__ float buf[1024];
    __shared__ float red[256];
    int t = threadIdx.x;
    float m = -1e30f;
    for (int i = t; i < L; i += 256) { float v = r[i]; buf[i] = v; m = fmaxf(m, v); }
    red[t] = m; __syncthreads();
    for (int o = 128; o > 0; o >>= 1) { if (t < o) red[t] = fmaxf(red[t], red[t + o]); __syncthreads(); }
    m = red[0]; __syncthreads();
    float s = 0.f;
    for (int i = t; i < L; i += 256) { float e = __expf(buf[i] - m); buf[i] = e; s += e; }
    red[t] = s; __syncthreads();
    for (int o = 128; o > 0; o >>= 1) { if (t < o) red[t] += red[t + o]; __syncthreads(); }
    float inv = 1.0f / red[0];
    for (int i = t; i < Lpad; i += 256) r[i] = (i < L) ? tfr(buf[i] * inv) : 0.f;
}

// ---------------------------------------------------------------------------
// Orchestration
// ---------------------------------------------------------------------------
extern "C" void kernel_launch(void* const* d_in, const int* in_sizes, int n_in,
                              void* d_out, int out_size)
{
    const float* x    = (const float*)d_in[0];
    const float* ctx  = (const float*)d_in[1];
    const float* sq_w = (const float*)d_in[2];
    const float* sk_w = (const float*)d_in[3];
    const float* sv_w = (const float*)d_in[4];
    const float* so_w = (const float*)d_in[5];
    const float* so_b = (const float*)d_in[6];
    const float* cq_w = (const float*)d_in[7];
    const float* ck_w = (const float*)d_in[8];
    const float* cv_w = (const float*)d_in[9];
    const float* co_w = (const float*)d_in[10];
    const float* co_b = (const float*)d_in[11];
    const float* n1_g = (const float*)d_in[12];
    const float* n1_b = (const float*)d_in[13];
    const float* n2_g = (const float*)d_in[14];
    const float* n2_b = (const float*)d_in[15];
    const float* n3_g = (const float*)d_in[16];
    const float* n3_b = (const float*)d_in[17];
    const float* n4_g = (const float*)d_in[18];
    const float* n4_b = (const float*)d_in[19];
    const float* f1_w1 = (const float*)d_in[20];
    const float* f1_b1 = (const float*)d_in[21];
    const float* f1_w2 = (const float*)d_in[22];
    const float* f1_b2 = (const float*)d_in[23];
    const float* f2_w1 = (const float*)d_in[24];
    const float* f2_b1 = (const float*)d_in[25];
    const float* f2_w2 = (const float*)d_in[26];
    const float* f2_b2 = (const float*)d_in[27];

    float *ln, *q, *k, *v, *attn, *h, *sc, *vts, *vtc, *ctxr, *wt;
    cudaGetSymbolAddress((void**)&ln,   g_ln);
    cudaGetSymbolAddress((void**)&q,    g_q);
    cudaGetSymbolAddress((void**)&k,    g_k);
    cudaGetSymbolAddress((void**)&v,    g_v);
    cudaGetSymbolAddress((void**)&attn, g_attn);
    cudaGetSymbolAddress((void**)&h,    g_h);
    cudaGetSymbolAddress((void**)&sc,   g_s);
    cudaGetSymbolAddress((void**)&vts,  g_vts);
    cudaGetSymbolAddress((void**)&vtc,  g_vtc);
    cudaGetSymbolAddress((void**)&ctxr, g_ctx);
    cudaGetSymbolAddress((void**)&wt,   g_wt);

    cudaFuncSetAttribute(mm_kernel<false,false>, cudaFuncAttributeMaxDynamicSharedMemorySize, SMEMSZ_);
    cudaFuncSetAttribute(mm_kernel<false,true >, cudaFuncAttributeMaxDynamicSharedMemorySize, SMEMSZ_);
    cudaFuncSetAttribute(mm_kernel<true ,true >, cudaFuncAttributeMaxDynamicSharedMemorySize, SMEMSZ_);

    float* X = (float*)d_out;
    const float scale = 0.125f;

    dim3 tb(32, 8);
    auto TW = [&](const float* w, float* o, int R, int C) {
        transpose_kernel<<<dim3((C + 31) / 32, (R + 31) / 32, 1), tb>>>(
            w, o, R, C, C, R, 0, 0, 0, 0, 1);
    };
    TW(sq_w, wt + WT_SQ, E_, E_);   TW(sk_w, wt + WT_SK, E_, E_);
    TW(sv_w, wt + WT_SV, E_, E_);   TW(so_w, wt + WT_SO, E_, E_);
    TW(cq_w, wt + WT_CQ, E_, E_);   TW(ck_w, wt + WT_CK, CD_, E_);
    TW(cv_w, wt + WT_CV, CD_, E_);  TW(co_w, wt + WT_CO, E_, E_);
    TW(f1_w1, wt + WT_F1A, E_, FF_); TW(f1_w2, wt + WT_F1B, FF_, E_);
    TW(f2_w1, wt + WT_F2A, E_, FF_); TW(f2_w2, wt + WT_F2B, FF_, E_);

    roundcopy4_kernel<<<(BS_ * CD_ / 4 + 255) / 256, 256>>>((const float4*)ctx, (float4*)ctxr, BS_ * CD_ / 4);

    // GEMM helper: C[M,N] = A[M,K] @ W (W^T supplied) + epi
    // mode: 0 = plain (no round), 1 = round output, 2 = gelu+round
    auto MM = [&](const float* A, const float* Bt, const float* bias,
                  const float* resid, float* C, int M, int N, int K,
                  int lda, int ldc, int mode) {
        dim3 g((N + 127) / 128, (M + 127) / 128, 1);
        if (mode == 2)
            mm_kernel<true,true><<<g, 256, SMEMSZ_>>>(A, Bt, bias, resid, C,
                M, N, N, K / 32, lda, K, ldc, 0, 0, 0, 0, 0, 0, 1, 1.f);
        else if (mode == 1)
            mm_kernel<false,true><<<g, 256, SMEMSZ_>>>(A, Bt, bias, resid, C,
                M, N, N, K / 32, lda, K, ldc, 0, 0, 0, 0, 0, 0, 1, 1.f);
        else
            mm_kernel<false,false><<<g, 256, SMEMSZ_>>>(A, Bt, bias, resid, C,
                M, N, N, K / 32, lda, K, ldc, 0, 0, 0, 0, 0, 0, 1, 1.f);
    };

    const long long TE = (long long)T_ * E_;

    // ================= self-attention =================
    ln_kernel<<<BT_, 256>>>(x, n1_g, n1_b, ln, E_);
    MM(ln, wt + WT_SQ, nullptr, nullptr, q, BT_, E_, E_, E_, E_, 1);
    MM(ln, wt + WT_SK, nullptr, nullptr, k, BT_, E_, E_, E_, E_, 1);
    MM(ln, wt + WT_SV, nullptr, nullptr, v, BT_, E_, E_, E_, E_, 1);
    transpose_kernel<<<dim3(2, 32, B_ * NH_), tb>>>(v, vts, T_, HD_, E_, T_,
        TE, HD_, (long long)NH_ * HD_ * T_, (long long)HD_ * T_, NH_);
    mm_kernel<false,false><<<dim3(8, 8, B_ * NH_), 256, SMEMSZ_>>>(q, k, nullptr, nullptr, sc,
        T_, T_, T_, HD_ / 32, E_, E_, T_,
        TE, HD_, TE, HD_, (long long)NH_ * T_ * T_, (long long)T_ * T_, NH_, scale);
    softmax_kernel<<<B_ * NH_ * T_, 256>>>(sc, T_, T_, T_);
    mm_kernel<false,true><<<dim3(1, 8, B_ * NH_), 256, SMEMSZ_>>>(sc, vts, nullptr, nullptr, attn,
        T_, HD_, HD_, T_ / 32, T_, T_, E_,
        (long long)NH_ * T_ * T_, (long long)T_ * T_,
        (long long)NH_ * HD_ * T_, (long long)HD_ * T_, TE, HD_, NH_, 1.f);
    MM(attn, wt + WT_SO, so_b, x, X, BT_, E_, E_, E_, E_, 0);   // resid = original x

    // ================= FFN 1 =================
    ln_kernel<<<BT_, 256>>>(X, n2_g, n2_b, ln, E_);
    MM(ln, wt + WT_F1A, f1_b1, nullptr, h, BT_, FF_, E_, E_, FF_, 2);
    MM(h, wt + WT_F1B, f1_b2, X, X, BT_, E_, FF_, FF_, E_, 0);

    // ================= cross-attention =================
    ln_kernel<<<BT_, 256>>>(X, n3_g, n3_b, ln, E_);
    MM(ln, wt + WT_CQ, nullptr, nullptr, q, BT_, E_, E_, E_, E_, 1);
    MM(ctxr, wt + WT_CK, nullptr, nullptr, k, BS_, E_, CD_, CD_, E_, 1);
    MM(ctxr, wt + WT_CV, nullptr, nullptr, v, BS_, E_, CD_, CD_, E_, 1);
    cudaMemsetAsync(vtc, 0, (size_t)B_ * NH_ * HD_ * SP_ * sizeof(float));
    transpose_kernel<<<dim3(2, 3, B_ * NH_), tb>>>(v, vtc, S_, HD_, E_, SP_,
        (long long)S_ * E_, HD_, (long long)NH_ * HD_ * SP_, (long long)HD_ * SP_, NH_);
    mm_kernel<false,false><<<dim3(1, 8, B_ * NH_), 256, SMEMSZ_>>>(q, k, nullptr, nullptr, sc,
        T_, S_, SP_, HD_ / 32, E_, E_, SP_,
        TE, HD_, (long long)S_ * E_, HD_,
        (long long)NH_ * T_ * SP_, (long long)T_ * SP_, NH_, scale);
    softmax_kernel<<<B_ * NH_ * T_, 256>>>(sc, S_, SP_, SP_);
    mm_kernel<false,true><<<dim3(1, 8, B_ * NH_), 256, SMEMSZ_>>>(sc, vtc, nullptr, nullptr, attn,
        T_, HD_, HD_, SP_ / 32, SP_, SP_, E_,
        (long long)NH_ * T_ * SP_, (long long)T_ * SP_,
        (long long)NH_ * HD_ * SP_, (long long)HD_ * SP_, TE, HD_, NH_, 1.f);
    MM(attn, wt + WT_CO, co_b, X, X, BT_, E_, E_, E_, E_, 0);

    // ================= FFN 2 =================
    ln_kernel<<<BT_, 256>>>(X, n4_g, n4_b, ln, E_);
    MM(ln, wt + WT_F2A, f2_b1, nullptr, h, BT_, FF_, E_, E_, FF_, 2);
    MM(h, wt + WT_F2B, f2_b2, X, X, BT_, E_, FF_, FF_, E_, 0);
}

// round 8
// speedup vs baseline: 6.4683x; 1.4183x over previous
#include <cuda_runtime.h>
#include <cuda_fp16.h>
#include <cstdint>
#include <math.h>

// ---------------------------------------------------------------------------
// TransformerBlock: B=4, T=1024, E=1024, NH=16, HD=64, ctx S=77 CD=768, FF=4096
// Round 6: fp16 mma.sync m16n8k16 (fp32 accum). Operands stored as half at
// production time; softmax input stays fp32.
// ---------------------------------------------------------------------------

#define B_   4
#define T_   1024
#define E_   1024
#define CD_  768
#define FF_  4096
#define NH_  16
#define HD_  64
#define S_   77
#define SP_  128
#define BT_  (B_ * T_)
#define BS_  (B_ * S_)

// ---- scratch --------------------------------------------------------------
__device__ __half g_ln[BT_ * E_];
__device__ __half g_q [BT_ * E_];
__device__ __half g_k [BT_ * E_];
__device__ __half g_v [BT_ * E_];
__device__ __half g_attn[BT_ * E_];
__device__ __half g_h [BT_ * FF_];
__device__ float  g_s [(size_t)B_ * NH_ * T_ * T_];     // fp32 scores
__device__ __half g_sh[(size_t)B_ * NH_ * T_ * T_];     // fp16 probs
__device__ __half g_vts[(size_t)B_ * NH_ * HD_ * T_];
__device__ __half g_vtc[(size_t)B_ * NH_ * HD_ * SP_];
__device__ __half g_ctx[BS_ * CD_];
__device__ __half g_wt[24 * 1024 * 1024];

#define WT_SQ   (0)
#define WT_SK   (1*1024*1024)
#define WT_SV   (2*1024*1024)
#define WT_SO   (3*1024*1024)
#define WT_CQ   (4*1024*1024)
#define WT_CK   (5*1024*1024)
#define WT_CV   (6*1024*1024)
#define WT_CO   (7*1024*1024)
#define WT_F1A  (8*1024*1024)
#define WT_F1B  (12*1024*1024)
#define WT_F2A  (16*1024*1024)
#define WT_F2B  (20*1024*1024)

// ---------------------------------------------------------------------------
// PTX helpers
// ---------------------------------------------------------------------------
__device__ __forceinline__ uint32_t s2u(const void* p) {
    uint32_t a;
    asm("{ .reg .u64 t; cvta.to.shared.u64 t, %1; cvt.u32.u64 %0, t; }" : "=r"(a) : "l"(p));
    return a;
}
#define CP16(dst, src, sz) \
    asm volatile("cp.async.cg.shared.global [%0], [%1], 16, %2;" \
                 :: "r"(dst), "l"(src), "r"(sz) : "memory")
#define CP_COMMIT() asm volatile("cp.async.commit_group;" ::: "memory")
#define CP_WAIT(n)  asm volatile("cp.async.wait_group %0;" :: "n"(n) : "memory")

__device__ __forceinline__ void mma16(float* c, const uint32_t* a, const uint32_t* b) {
    asm volatile(
        "mma.sync.aligned.m16n8k16.row.col.f32.f16.f16.f32 "
        "{%0,%1,%2,%3},{%4,%5,%6,%7},{%8,%9},{%0,%1,%2,%3};"
        : "+f"(c[0]), "+f"(c[1]), "+f"(c[2]), "+f"(c[3])
        : "r"(a[0]), "r"(a[1]), "r"(a[2]), "r"(a[3]), "r"(b[0]), "r"(b[1]));
}

// ---------------------------------------------------------------------------
// fp16 GEMM (fp32 accum): D[m,n] = sum_k A[m,k] * B[n,k]   (B K-major = W^T)
// CTA tile 128x128, K-chunk 32, 8 warps (2x4), warp tile 64x32, 2-stage.
// PADH=40 halves: fragment half2 LDS are conflict-free.
// ---------------------------------------------------------------------------
#define PADH_ 40
#define ASH_  (128 * PADH_)            // halves per tile
#define SMEMSZ_ (4 * ASH_ * 2)         // bytes: A0,B0,A1,B1

template <bool GELU, typename OutT>
__global__ __launch_bounds__(256) void mm_kernel(
    const __half* __restrict__ A, const __half* __restrict__ Bm,
    const float* __restrict__ bias, const float* __restrict__ resid,
    OutT* __restrict__ C,
    int M, int Nload, int Nstore, int Kch, int lda, int ldb, int ldc,
    long long aOuter, long long aInner, long long bOuter, long long bInner,
    long long cOuter, long long cInner, int NHz, float scale)
{
    extern __shared__ __half smem[];
    const uint32_t sbase = s2u(smem);

    const int tid = threadIdx.x;
    const int wid = tid >> 5, lane = tid & 31;
    const int grp = lane >> 2, tig = lane & 3;
    const int mW = (wid >> 2) * 64, nW = (wid & 3) * 32;

    const int z = blockIdx.z;
    const int zb = z / NHz, zh = z % NHz;
    const __half* Ab = A + zb * aOuter + zh * aInner;
    const __half* Bb = Bm + zb * bOuter + zh * bInner;
    OutT* Cb = C + zb * cOuter + zh * cInner;
    const float* Rb = resid ? resid + zb * cOuter + zh * cInner : nullptr;

    const int bm = blockIdx.y * 128, bn = blockIdx.x * 128;

    float acc[4][4][4];
    #pragma unroll
    for (int i = 0; i < 4; i++)
        #pragma unroll
        for (int j = 0; j < 4; j++)
            #pragma unroll
            for (int e = 0; e < 4; e++) acc[i][j][e] = 0.f;

    // load A/B 128x32-half tiles into stage st (16B segments, 4 per row)
    auto loadChunk = [&](int ic, int st) {
        const int k0 = ic * 32;
        const uint32_t aB = sbase + (uint32_t)st * 2u * ASH_ * 2u;
        const uint32_t bB = aB + ASH_ * 2u;
        #pragma unroll
        for (int i = 0; i < 4; i++) {
            int seg = tid + i * 256;           // 0..1023; 0-511 A, 512-1023 B
            int isB = seg >> 9;
            int s4  = seg & 511;
            int row = s4 >> 2, s = s4 & 3;     // 128 rows x 4 segs(8 halves)
            if (!isB) {
                int gm = bm + row;
                const __half* src = Ab + (size_t)(gm < M ? gm : 0) * lda + k0 + s * 8;
                CP16(aB + (uint32_t)(row * PADH_ + s * 8) * 2u, src, (gm < M) ? 16 : 0);
            } else {
                int gn = bn + row;
                const __half* src = Bb + (size_t)(gn < Nload ? gn : 0) * ldb + k0 + s * 8;
                CP16(bB + (uint32_t)(row * PADH_ + s * 8) * 2u, src, (gn < Nload) ? 16 : 0);
            }
        }
        CP_COMMIT();
    };

    loadChunk(0, 0);

    for (int ic = 0; ic < Kch; ic++) {
        const int st = ic & 1;
        if (ic + 1 < Kch) { loadChunk(ic + 1, st ^ 1); CP_WAIT(1); }
        else             { CP_WAIT(0); }
        __syncthreads();

        const __half* As_ = smem + st * 2 * ASH_;
        const __half* Bs_ = As_ + ASH_;

        #pragma unroll
        for (int t16 = 0; t16 < 2; t16++) {
            const int k = t16 * 16 + 2 * tig;
            uint32_t af[4][4], bf[4][2];
            #pragma unroll
            for (int mt = 0; mt < 4; mt++) {
                int r = mW + mt * 16 + grp;
                af[mt][0] = *(const uint32_t*)&As_[r * PADH_ + k];
                af[mt][1] = *(const uint32_t*)&As_[(r + 8) * PADH_ + k];
                af[mt][2] = *(const uint32_t*)&As_[r * PADH_ + k + 8];
                af[mt][3] = *(const uint32_t*)&As_[(r + 8) * PADH_ + k + 8];
            }
            #pragma unroll
            for (int nt = 0; nt < 4; nt++) {
                int n = nW + nt * 8 + grp;
                bf[nt][0] = *(const uint32_t*)&Bs_[n * PADH_ + k];
                bf[nt][1] = *(const uint32_t*)&Bs_[n * PADH_ + k + 8];
            }
            #pragma unroll
            for (int mt = 0; mt < 4; mt++)
                #pragma unroll
                for (int nt = 0; nt < 4; nt++)
                    mma16(acc[mt][nt], af[mt], bf[nt]);
        }
        __syncthreads();
    }

    // ---- epilogue ----
    #pragma unroll
    for (int mt = 0; mt < 4; mt++) {
        #pragma unroll
        for (int half_ = 0; half_ < 2; half_++) {
            int row = bm + mW + mt * 16 + grp + half_ * 8;
            if (row >= M) continue;
            OutT* crow = Cb + (size_t)row * ldc;
            const float* rrow = Rb ? Rb + (size_t)row * ldc : nullptr;
            #pragma unroll
            for (int nt = 0; nt < 4; nt++) {
                int col = bn + nW + nt * 8 + 2 * tig;
                if (col >= Nstore) continue;
                float v0 = acc[mt][nt][half_ * 2 + 0] * scale;
                float v1 = acc[mt][nt][half_ * 2 + 1] * scale;
                if (bias) { v0 += bias[col]; v1 += bias[col + 1]; }
                if (GELU) {
                    v0 = 0.5f * v0 * (1.0f + erff(v0 * 0.70710678118654752f));
                    v1 = 0.5f * v1 * (1.0f + erff(v1 * 0.70710678118654752f));
                }
                if (rrow) { v0 += rrow[col]; v1 += rrow[col + 1]; }
                if (col + 1 < Nstore) {
                    if (sizeof(OutT) == 2) {
                        __half2 hv = __floats2half2_rn(v0, v1);
                        *(__half2*)(crow + col) = hv;
                    } else {
                        *(float2*)((float*)crow + col) = make_float2(v0, v1);
                    }
                } else {
                    crow[col] = (OutT)v0;
                }
            }
        }
    }
}

// ---------------------------------------------------------------------------
// Transpose (batched): InT -> half. block (32,8)
// ---------------------------------------------------------------------------
template <typename InT>
__global__ void transpose_kernel(
    const InT* __restrict__ in, __half* __restrict__ out,
    int R, int C, int ldi, int ldo,
    long long iOuter, long long iInner, long long oOuter, long long oInner, int NHz)
{
    __shared__ float t[32][33];
    int z = blockIdx.z, zb = z / NHz, zh = z % NHz;
    const InT* ib = in + zb * iOuter + zh * iInner;
    __half* ob = out + zb * oOuter + zh * oInner;
    int c0 = blockIdx.x * 32, r0 = blockIdx.y * 32;
    int x = threadIdx.x, y = threadIdx.y;
    #pragma unroll
    for (int j = 0; j < 32; j += 8) {
        int r = r0 + y + j, c = c0 + x;
        t[y + j][x] = (r < R && c < C) ? (float)ib[(size_t)r * ldi + c] : 0.f;
    }
    __syncthreads();
    #pragma unroll
    for (int j = 0; j < 32; j += 8) {
        int oc = r0 + x, orow = c0 + y + j;
        if (orow < C && oc < R) ob[(size_t)orow * ldo + oc] = __float2half_rn(t[x][y + j]);
    }
}

// round-copy float -> half (for ctx)
__global__ void h_copy_kernel(const float2* __restrict__ in, __half2* __restrict__ out, int n2) {
    int i = blockIdx.x * blockDim.x + threadIdx.x;
    if (i < n2) {
        float2 v = in[i];
        out[i] = __floats2half2_rn(v.x, v.y);
    }
}

// ---------------------------------------------------------------------------
// LayerNorm (float in, half out) / softmax (float in, half out)
// ---------------------------------------------------------------------------
__global__ __launch_bounds__(256) void ln_kernel(
    const float* __restrict__ x, const float* __restrict__ g,
    const float* __restrict__ b, __half* __restrict__ out, int N)
{
    int row = blockIdx.x;
    const float* xr = x + (size_t)row * N;
    __half* orow = out + (size_t)row * N;
    int t = threadIdx.x;
    float s = 0.f, s2 = 0.f;
    for (int i = t; i < N; i += 256) { float v = xr[i]; s += v; s2 += v * v; }
    __shared__ float rs[256], rs2[256];
    rs[t] = s; rs2[t] = s2; __syncthreads();
    for (int o = 128; o > 0; o >>= 1) {
        if (t < o) { rs[t] += rs[t + o]; rs2[t] += rs2[t + o]; }
        __syncthreads();
    }
    float mean = rs[0] / N;
    float var = rs2[0] / N - mean * mean;
    float inv = rsqrtf(var + 1e-5f);
    for (int i = t; i < N; i += 256)
        orow[i] = __float2half_rn((xr[i] - mean) * inv * g[i] + b[i]);
}

__global__ __launch_bounds__(256) void softmax_kernel(
    const float* __restrict__ Sin, __half* __restrict__ Sout,
    int L, int Lpad, int stride)
{
    const float* r = Sin + (size_t)blockIdx.x * stride;
    __half* w = Sout + (size_t)blockIdx.x * stride;
    __shared__ float buf[1024];
    __shared__ float red[256];
    int t = threadIdx.x;
    float m = -1e30f;
    for (int i = t; i < L; i += 256) { float v = r[i]; buf[i] = v; m = fmaxf(m, v); }
    red[t] = m; __syncthreads();
    for (int o = 128; o > 0; o >>= 1) { if (t < o) red[t] = fmaxf(red[t], red[t + o]); __syncthreads(); }
    m = red[0]; __syncthreads();
    float s = 0.f;
    for (int i = t; i < L; i += 256) { float e = __expf(buf[i] - m); buf[i] = e; s += e; }
    red[t] = s; __syncthreads();
    for (int o = 128; o > 0; o >>= 1) { if (t < o) red[t] += red[t + o]; __syncthreads(); }
    float inv = 1.0f / red[0];
    for (int i = t; i < Lpad; i += 256)
        w[i] = (i < L) ? __float2half_rn(buf[i] * inv) : __float2half_rn(0.f);
}

// ---------------------------------------------------------------------------
// Orchestration
// ---------------------------------------------------------------------------
extern "C" void kernel_launch(void* const* d_in, const int* in_sizes, int n_in,
                              void* d_out, int out_size)
{
    const float* x    = (const float*)d_in[0];
    const float* ctx  = (const float*)d_in[1];
    const float* sq_w = (const float*)d_in[2];
    const float* sk_w = (const float*)d_in[3];
    const float* sv_w = (const float*)d_in[4];
    const float* so_w = (const float*)d_in[5];
    const float* so_b = (const float*)d_in[6];
    const float* cq_w = (const float*)d_in[7];
    const float* ck_w = (const float*)d_in[8];
    const float* cv_w = (const float*)d_in[9];
    const float* co_w = (const float*)d_in[10];
    const float* co_b = (const float*)d_in[11];
    const float* n1_g = (const float*)d_in[12];
    const float* n1_b = (const float*)d_in[13];
    const float* n2_g = (const float*)d_in[14];
    const float* n2_b = (const float*)d_in[15];
    const float* n3_g = (const float*)d_in[16];
    const float* n3_b = (const float*)d_in[17];
    const float* n4_g = (const float*)d_in[18];
    const float* n4_b = (const float*)d_in[19];
    const float* f1_w1 = (const float*)d_in[20];
    const float* f1_b1 = (const float*)d_in[21];
    const float* f1_w2 = (const float*)d_in[22];
    const float* f1_b2 = (const float*)d_in[23];
    const float* f2_w1 = (const float*)d_in[24];
    const float* f2_b1 = (const float*)d_in[25];
    const float* f2_w2 = (const float*)d_in[26];
    const float* f2_b2 = (const float*)d_in[27];

    __half *ln, *q, *k, *v, *attn, *h, *sh, *vts, *vtc, *ctxr, *wt;
    float *sc;
    cudaGetSymbolAddress((void**)&ln,   g_ln);
    cudaGetSymbolAddress((void**)&q,    g_q);
    cudaGetSymbolAddress((void**)&k,    g_k);
    cudaGetSymbolAddress((void**)&v,    g_v);
    cudaGetSymbolAddress((void**)&attn, g_attn);
    cudaGetSymbolAddress((void**)&h,    g_h);
    cudaGetSymbolAddress((void**)&sc,   g_s);
    cudaGetSymbolAddress((void**)&sh,   g_sh);
    cudaGetSymbolAddress((void**)&vts,  g_vts);
    cudaGetSymbolAddress((void**)&vtc,  g_vtc);
    cudaGetSymbolAddress((void**)&ctxr, g_ctx);
    cudaGetSymbolAddress((void**)&wt,   g_wt);

    cudaFuncSetAttribute(mm_kernel<false,float >, cudaFuncAttributeMaxDynamicSharedMemorySize, SMEMSZ_);
    cudaFuncSetAttribute(mm_kernel<false,__half>, cudaFuncAttributeMaxDynamicSharedMemorySize, SMEMSZ_);
    cudaFuncSetAttribute(mm_kernel<true ,__half>, cudaFuncAttributeMaxDynamicSharedMemorySize, SMEMSZ_);

    float* X = (float*)d_out;
    const float scale = 0.125f;

    dim3 tb(32, 8);
    auto TW = [&](const float* w, __half* o, int R, int C) {
        transpose_kernel<float><<<dim3((C + 31) / 32, (R + 31) / 32, 1), tb>>>(
            w, o, R, C, C, R, 0, 0, 0, 0, 1);
    };
    TW(sq_w, wt + WT_SQ, E_, E_);   TW(sk_w, wt + WT_SK, E_, E_);
    TW(sv_w, wt + WT_SV, E_, E_);   TW(so_w, wt + WT_SO, E_, E_);
    TW(cq_w, wt + WT_CQ, E_, E_);   TW(ck_w, wt + WT_CK, CD_, E_);
    TW(cv_w, wt + WT_CV, CD_, E_);  TW(co_w, wt + WT_CO, E_, E_);
    TW(f1_w1, wt + WT_F1A, E_, FF_); TW(f1_w2, wt + WT_F1B, FF_, E_);
    TW(f2_w1, wt + WT_F2A, E_, FF_); TW(f2_w2, wt + WT_F2B, FF_, E_);

    h_copy_kernel<<<(BS_ * CD_ / 2 + 255) / 256, 256>>>((const float2*)ctx, (__half2*)ctxr, BS_ * CD_ / 2);

    // GEMM helper. mode: 0 = float out (+opt resid), 1 = half out, 2 = gelu+half out
    auto MM = [&](const __half* A, const __half* Bt, const float* bias,
                  const float* resid, void* C, int M, int N, int K,
                  int lda, int ldc, int mode) {
        dim3 g((N + 127) / 128, (M + 127) / 128, 1);
        if (mode == 2)
            mm_kernel<true,__half><<<g, 256, SMEMSZ_>>>(A, Bt, bias, resid, (__half*)C,
                M, N, N, K / 32, lda, K, ldc, 0, 0, 0, 0, 0, 0, 1, 1.f);
        else if (mode == 1)
            mm_kernel<false,__half><<<g, 256, SMEMSZ_>>>(A, Bt, bias, resid, (__half*)C,
                M, N, N, K / 32, lda, K, ldc, 0, 0, 0, 0, 0, 0, 1, 1.f);
        else
            mm_kernel<false,float><<<g, 256, SMEMSZ_>>>(A, Bt, bias, resid, (float*)C,
                M, N, N, K / 32, lda, K, ldc, 0, 0, 0, 0, 0, 0, 1, 1.f);
    };

    const long long TE = (long long)T_ * E_;

    // ================= self-attention =================
    ln_kernel<<<BT_, 256>>>(x, n1_g, n1_b, ln, E_);
    MM(ln, wt + WT_SQ, nullptr, nullptr, q, BT_, E_, E_, E_, E_, 1);
    MM(ln, wt + WT_SK, nullptr, nullptr, k, BT_, E_, E_, E_, E_, 1);
    MM(ln, wt + WT_SV, nullptr, nullptr, v, BT_, E_, E_, E_, E_, 1);
    transpose_kernel<__half><<<dim3(2, 32, B_ * NH_), tb>>>(v, vts, T_, HD_, E_, T_,
        TE, HD_, (long long)NH_ * HD_ * T_, (long long)HD_ * T_, NH_);
    mm_kernel<false,float><<<dim3(8, 8, B_ * NH_), 256, SMEMSZ_>>>(q, k, nullptr, nullptr, sc,
        T_, T_, T_, HD_ / 32, E_, E_, T_,
        TE, HD_, TE, HD_, (long long)NH_ * T_ * T_, (long long)T_ * T_, NH_, scale);
    softmax_kernel<<<B_ * NH_ * T_, 256>>>(sc, sh, T_, T_, T_);
    mm_kernel<false,__half><<<dim3(1, 8, B_ * NH_), 256, SMEMSZ_>>>(sh, vts, nullptr, nullptr, attn,
        T_, HD_, HD_, T_ / 32, T_, T_, E_,
        (long long)NH_ * T_ * T_, (long long)T_ * T_,
        (long long)NH_ * HD_ * T_, (long long)HD_ * T_, TE, HD_, NH_, 1.f);
    MM(attn, wt + WT_SO, so_b, x, X, BT_, E_, E_, E_, E_, 0);   // resid = original x

    // ================= FFN 1 =================
    ln_kernel<<<BT_, 256>>>(X, n2_g, n2_b, ln, E_);
    MM(ln, wt + WT_F1A, f1_b1, nullptr, h, BT_, FF_, E_, E_, FF_, 2);
    MM(h, wt + WT_F1B, f1_b2, X, X, BT_, E_, FF_, FF_, E_, 0);

    // ================= cross-attention =================
    ln_kernel<<<BT_, 256>>>(X, n3_g, n3_b, ln, E_);
    MM(ln, wt + WT_CQ, nullptr, nullptr, q, BT_, E_, E_, E_, E_, 1);
    MM(ctxr, wt + WT_CK, nullptr, nullptr, k, BS_, E_, CD_, CD_, E_, 1);
    MM(ctxr, wt + WT_CV, nullptr, nullptr, v, BS_, E_, CD_, CD_, E_, 1);
    cudaMemsetAsync(vtc, 0, (size_t)B_ * NH_ * HD_ * SP_ * sizeof(__half));
    transpose_kernel<__half><<<dim3(2, 3, B_ * NH_), tb>>>(v, vtc, S_, HD_, E_, SP_,
        (long long)S_ * E_, HD_, (long long)NH_ * HD_ * SP_, (long long)HD_ * SP_, NH_);
    mm_kernel<false,float><<<dim3(1, 8, B_ * NH_), 256, SMEMSZ_>>>(q, k, nullptr, nullptr, sc,
        T_, S_, SP_, HD_ / 32, E_, E_, SP_,
        TE, HD_, (long long)S_ * E_, HD_,
        (long long)NH_ * T_ * SP_, (long long)T_ * SP_, NH_, scale);
    softmax_kernel<<<B_ * NH_ * T_, 256>>>(sc, sh, S_, SP_, SP_);
    mm_kernel<false,__half><<<dim3(1, 8, B_ * NH_), 256, SMEMSZ_>>>(sh, vtc, nullptr, nullptr, attn,
        T_, HD_, HD_, SP_ / 32, SP_, SP_, E_,
        (long long)NH_ * T_ * SP_, (long long)T_ * SP_,
        (long long)NH_ * HD_ * SP_, (long long)HD_ * SP_, TE, HD_, NH_, 1.f);
    MM(attn, wt + WT_CO, co_b, X, X, BT_, E_, E_, E_, E_, 0);

    // ================= FFN 2 =================
    ln_kernel<<<BT_, 256>>>(X, n4_g, n4_b, ln, E_);
    MM(ln, wt + WT_F2A, f2_b1, nullptr, h, BT_, FF_, E_, E_, FF_, 2);
    MM(h, wt + WT_F2B, f2_b2, X, X, BT_, E_, FF_, FF_, E_, 0);
}